// round 1
// baseline (speedup 1.0000x reference)
#include <cuda_runtime.h>
#include <cuda_bf16.h>
#include <stdint.h>

// Problem constants (fixed by the reference)
#define NN 250000
#define DD 128
#define FF 512
#define BB 5000

// Per-bag argmax keys: (ordered_float(loc) << 32) | ~row_index
// atomicMax picks max loc; among exactly-equal locs, max(~row) = min row.
// 0 is a safe "empty" sentinel: any real key has low word ~row >= ~(N-1) != 0.
__device__ unsigned long long g_keys[BB];

__global__ void init_keys_kernel() {
    int i = blockIdx.x * blockDim.x + threadIdx.x;
    if (i < BB) g_keys[i] = 0ULL;
}

__device__ __forceinline__ unsigned ordered_float(float f) {
    unsigned u = __float_as_uint(f);
    return u ^ (((int)u >> 31) | 0x80000000u);
}

__device__ __forceinline__ float dot4(float4 a, float4 b) {
    return fmaf(a.x, b.x, fmaf(a.y, b.y, fmaf(a.z, b.z, a.w * b.w)));
}

// Warp-per-row matvec: loc = z[row] . W + b ; write loc_ins; atomic argmax per bag.
__global__ void matvec_argmax_kernel(const float* __restrict__ z,
                                     const int*   __restrict__ bag,
                                     const float* __restrict__ W,
                                     const float* __restrict__ bptr,
                                     float* __restrict__ loc_out,
                                     int n) {
    const int lane   = threadIdx.x & 31;
    const int warp   = (blockIdx.x * blockDim.x + threadIdx.x) >> 5;
    const int nwarps = (gridDim.x * blockDim.x) >> 5;

    // W: 128 floats -> one float4 per lane, stays in registers
    const float4 w4   = reinterpret_cast<const float4*>(W)[lane];
    const float  bias = bptr[0];
    const float4* z4p = reinterpret_cast<const float4*>(z); // 32 float4 per row

    // 2 rows in flight per warp iteration (MLP=2)
    for (int row = warp; row < n; row += 2 * nwarps) {
        const int row2 = row + nwarps;
        const bool has2 = (row2 < n);

        float4 a = z4p[(size_t)row * 32 + lane];
        float4 c;
        if (has2) c = z4p[(size_t)row2 * 32 + lane];

        float s1 = dot4(a, w4);
        float s2 = has2 ? dot4(c, w4) : 0.0f;

        #pragma unroll
        for (int o = 16; o > 0; o >>= 1) {
            s1 += __shfl_xor_sync(0xFFFFFFFFu, s1, o);
            s2 += __shfl_xor_sync(0xFFFFFFFFu, s2, o);
        }
        s1 += bias;
        s2 += bias;

        if (lane == 0) {
            loc_out[row] = s1;
            unsigned long long k1 =
                ((unsigned long long)ordered_float(s1) << 32) | (unsigned)(~row);
            atomicMax(&g_keys[bag[row]], k1);
            if (has2) {
                loc_out[row2] = s2;
                unsigned long long k2 =
                    ((unsigned long long)ordered_float(s2) << 32) | (unsigned)(~row2);
                atomicMax(&g_keys[bag[row2]], k2);
            }
        }
    }
}

// One block per bag: decode argmax, gather all outputs.
__global__ void gather_kernel(const float* __restrict__ z,
                              const float* __restrict__ inst,
                              const float* __restrict__ mu,
                              const float* __restrict__ sd,
                              float* __restrict__ out) {
    const int bagId = blockIdx.x;
    const int tid   = threadIdx.x; // 256 threads

    const unsigned long long key = g_keys[bagId];
    const bool empty = (key == 0ULL);
    int idx = (int)(~(unsigned)(key & 0xFFFFFFFFull));
    if (empty) idx = 0; // avoid OOB reads; values forced to 0 below

    // Output layout: M | max_instances | max_z_ins | loc_ins | max_mu | max_std
    float* M_out    = out;
    float* inst_out = out + BB;
    float* z_out    = inst_out + (size_t)BB * FF;
    float* loc_buf  = z_out    + (size_t)BB * DD;   // loc_ins region (already written)
    float* mu_out   = loc_buf  + NN;
    float* sd_out   = mu_out   + (size_t)BB * DD;

    const float zero = 0.0f;

    const float* srcI = inst + (size_t)idx * FF;
    #pragma unroll
    for (int j = tid; j < FF; j += 256)
        inst_out[(size_t)bagId * FF + j] = empty ? zero : srcI[j];

    if (tid < DD) {
        z_out [(size_t)bagId * DD + tid] = empty ? zero : z [(size_t)idx * DD + tid];
        mu_out[(size_t)bagId * DD + tid] = empty ? zero : mu[(size_t)idx * DD + tid];
        sd_out[(size_t)bagId * DD + tid] = empty ? zero : sd[(size_t)idx * DD + tid];
    }
    if (tid == 0)
        M_out[bagId] = empty ? zero : loc_buf[idx];
}

extern "C" void kernel_launch(void* const* d_in, const int* in_sizes, int n_in,
                              void* d_out, int out_size) {
    const float* z    = (const float*)d_in[0]; // z_ins (N,D)
    const int*   bag  = (const int*)  d_in[1]; // bag_idx (N,)
    const float* inst = (const float*)d_in[2]; // bag_instances (N,F)
    const float* mu   = (const float*)d_in[3]; // instance_mu (N,D)
    const float* sd   = (const float*)d_in[4]; // instance_std (N,D)
    const float* W    = (const float*)d_in[5]; // (D,1)
    const float* b    = (const float*)d_in[6]; // (1,)
    float* out = (float*)d_out;

    const int n = in_sizes[1]; // N from bag_idx element count

    float* loc_out = out + BB + (size_t)BB * FF + (size_t)BB * DD;

    init_keys_kernel<<<(BB + 255) / 256, 256>>>();
    matvec_argmax_kernel<<<2048, 256>>>(z, bag, W, b, loc_out, n);
    gather_kernel<<<BB, 256>>>(z, inst, mu, sd, out);
}

// round 2
// speedup vs baseline: 1.1374x; 1.1374x over previous
#include <cuda_runtime.h>
#include <cuda_bf16.h>
#include <stdint.h>

// Problem constants (fixed by the reference)
#define NN 250000
#define DD 128
#define FF 512
#define BB 5000

// Per-bag argmax keys: (ordered_float(loc) << 32) | ~row_index
// atomicMax picks max loc; ties -> max(~row) = min row.
// 0 is a safe "empty" sentinel (any real low word ~row != 0).
// Zeroed at module load; gather_kernel re-zeros after consuming, so every
// graph replay starts from the all-zero state (no init kernel needed).
__device__ unsigned long long g_keys[BB];

__device__ __forceinline__ unsigned ordered_float(float f) {
    unsigned u = __float_as_uint(f);
    return u ^ (((int)u >> 31) | 0x80000000u);
}

__device__ __forceinline__ float dot4(float4 a, float4 b) {
    return fmaf(a.x, b.x, fmaf(a.y, b.y, fmaf(a.z, b.z, a.w * b.w)));
}

// Quad-per-row matvec: 4 lanes per row, 8 rows per warp per iteration.
// Each lane: 8 independent LDG.128 (MLP=8), 32 FFMA, 2 SHFL.
__global__ void matvec_argmax_kernel(const float* __restrict__ z,
                                     const int*   __restrict__ bag,
                                     const float* __restrict__ W,
                                     const float* __restrict__ bptr,
                                     float* __restrict__ loc_out,
                                     int n) {
    const int lane   = threadIdx.x & 31;
    const int q      = lane & 3;        // position within quad (0..3)
    const int quad   = lane >> 2;       // quad id within warp (0..7)
    const int warp   = (blockIdx.x * blockDim.x + threadIdx.x) >> 5;
    const int nwarps = (gridDim.x * blockDim.x) >> 5;

    // W registers: this lane needs w4[q + 4k], k=0..7 (8 float4)
    const float4* W4 = reinterpret_cast<const float4*>(W);
    float4 w[8];
    #pragma unroll
    for (int k = 0; k < 8; k++) w[k] = W4[q + 4 * k];

    const float  bias = bptr[0];
    const float4* z4p = reinterpret_cast<const float4*>(z); // 32 float4 per row

    // warp handles rows [warp*8 + quad], grid-stride by nwarps*8
    for (int rowBase = warp * 8; rowBase < n; rowBase += nwarps * 8) {
        const int row = rowBase + quad;
        const bool valid = (row < n);

        float s = 0.0f;
        if (valid) {
            const float4* zr = z4p + (size_t)row * 32;
            float4 a[8];
            #pragma unroll
            for (int k = 0; k < 8; k++) a[k] = zr[q + 4 * k];
            #pragma unroll
            for (int k = 0; k < 8; k++) s += dot4(a[k], w[k]);
        }
        // reduce across the 4 lanes of the quad
        s += __shfl_xor_sync(0xFFFFFFFFu, s, 1);
        s += __shfl_xor_sync(0xFFFFFFFFu, s, 2);
        s += bias;

        if (valid && q == 0) {
            loc_out[row] = s;
            unsigned long long key =
                ((unsigned long long)ordered_float(s) << 32) | (unsigned)(~row);
            atomicMax(&g_keys[bag[row]], key);
        }
    }
}

// One block (128 threads) per bag: decode argmax, gather outputs, reset key.
__global__ void gather_kernel(const float* __restrict__ z,
                              const float* __restrict__ inst,
                              const float* __restrict__ mu,
                              const float* __restrict__ sd,
                              float* __restrict__ out) {
    const int bagId = blockIdx.x;
    const int tid   = threadIdx.x; // 128 threads

    const unsigned long long key = g_keys[bagId];
    __syncthreads();                 // everyone has read the key
    if (tid == 0) g_keys[bagId] = 0; // restore zero state for next replay

    const bool empty = (key == 0ULL);
    int idx = (int)(~(unsigned)(key & 0xFFFFFFFFull));
    if (empty) idx = 0; // avoid OOB reads; values forced to 0 below

    // Output layout: M | max_instances | max_z_ins | loc_ins | max_mu | max_std
    float* M_out    = out;
    float* inst_out = out + BB;
    float* z_out    = inst_out + (size_t)BB * FF;
    float* loc_buf  = z_out    + (size_t)BB * DD;   // loc_ins (written by matvec)
    float* mu_out   = loc_buf  + NN;
    float* sd_out   = mu_out   + (size_t)BB * DD;

    const float4 zero4 = make_float4(0.f, 0.f, 0.f, 0.f);

    // max_instances: 512 floats = 128 float4, exactly one per thread
    {
        const float4* src = reinterpret_cast<const float4*>(inst + (size_t)idx * FF);
        float4* dst = reinterpret_cast<float4*>(inst_out + (size_t)bagId * FF);
        dst[tid] = empty ? zero4 : src[tid];
    }

    // z / mu / sd: 32 float4 each, disjoint 32-thread groups
    if (tid < 32) {
        const float4* src = reinterpret_cast<const float4*>(z + (size_t)idx * DD);
        float4* dst = reinterpret_cast<float4*>(z_out + (size_t)bagId * DD);
        dst[tid] = empty ? zero4 : src[tid];
    } else if (tid < 64) {
        const int t = tid - 32;
        const float4* src = reinterpret_cast<const float4*>(mu + (size_t)idx * DD);
        float4* dst = reinterpret_cast<float4*>(mu_out + (size_t)bagId * DD);
        dst[t] = empty ? zero4 : src[t];
    } else if (tid < 96) {
        const int t = tid - 64;
        const float4* src = reinterpret_cast<const float4*>(sd + (size_t)idx * DD);
        float4* dst = reinterpret_cast<float4*>(sd_out + (size_t)bagId * DD);
        dst[t] = empty ? zero4 : src[t];
    } else if (tid == 96) {
        M_out[bagId] = empty ? 0.0f : loc_buf[idx];
    }
}

extern "C" void kernel_launch(void* const* d_in, const int* in_sizes, int n_in,
                              void* d_out, int out_size) {
    const float* z    = (const float*)d_in[0]; // z_ins (N,D)
    const int*   bag  = (const int*)  d_in[1]; // bag_idx (N,)
    const float* inst = (const float*)d_in[2]; // bag_instances (N,F)
    const float* mu   = (const float*)d_in[3]; // instance_mu (N,D)
    const float* sd   = (const float*)d_in[4]; // instance_std (N,D)
    const float* W    = (const float*)d_in[5]; // (D,1)
    const float* b    = (const float*)d_in[6]; // (1,)
    float* out = (float*)d_out;

    const int n = in_sizes[1]; // N from bag_idx element count

    float* loc_out = out + BB + (size_t)BB * FF + (size_t)BB * DD;

    matvec_argmax_kernel<<<2048, 256>>>(z, bag, W, b, loc_out, n);
    gather_kernel<<<BB, 128>>>(z, inst, mu, sd, out);
}

// round 3
// speedup vs baseline: 1.3426x; 1.1804x over previous
#include <cuda_runtime.h>
#include <cuda_bf16.h>
#include <stdint.h>

#define NN 250000
#define DD 128
#define FF 512
#define BB 5000

// Per-bag argmax keys: (ordered_float(loc) << 32) | ~row_index
// atomicMax picks max loc; ties -> max(~row) = min row.
// 0 is a safe "empty" sentinel. Zeroed at module load; gather_kernel re-zeros
// after consuming, so every graph replay starts from the all-zero state.
__device__ unsigned long long g_keys[BB];

__device__ __forceinline__ unsigned ordered_float(float f) {
    unsigned u = __float_as_uint(f);
    return u ^ (((int)u >> 31) | 0x80000000u);
}

__device__ __forceinline__ float dot4(float4 a, float4 b) {
    return fmaf(a.x, b.x, fmaf(a.y, b.y, fmaf(a.z, b.z, a.w * b.w)));
}

// Quad-per-row matvec: 4 lanes per row, 8 consecutive rows per warp iteration.
// bag_idx is SORTED, so the warp's 8 rows span ~1-2 bags: aggregate the
// argmax per distinct bag inside the warp and issue ONE atomic per bag,
// cutting global atomics ~8x (same-address L2 atomic serialization relief).
__global__ void matvec_argmax_kernel(const float* __restrict__ z,
                                     const int*   __restrict__ bag,
                                     const float* __restrict__ W,
                                     const float* __restrict__ bptr,
                                     float* __restrict__ loc_out,
                                     int n) {
    const int lane   = threadIdx.x & 31;
    const int q      = lane & 3;        // position within quad (0..3)
    const int quad   = lane >> 2;       // quad id within warp (0..7)
    const int warp   = (blockIdx.x * blockDim.x + threadIdx.x) >> 5;
    const int nwarps = (gridDim.x * blockDim.x) >> 5;

    // W registers: this lane needs W4[q + 4k], k=0..7
    const float4* W4 = reinterpret_cast<const float4*>(W);
    float4 w[8];
    #pragma unroll
    for (int k = 0; k < 8; k++) w[k] = W4[q + 4 * k];

    const float  bias = bptr[0];
    const float4* z4p = reinterpret_cast<const float4*>(z); // 32 float4 per row

    for (int rowBase = warp * 8; rowBase < n; rowBase += nwarps * 8) {
        const int row = rowBase + quad;
        const bool valid = (row < n);

        float s = 0.0f;
        int   bg = -1;
        if (valid) {
            const float4* zr = z4p + (size_t)row * 32;
            float4 a[8];
            #pragma unroll
            for (int k = 0; k < 8; k++)
                a[k] = __ldcs(zr + q + 4 * k);      // streaming: read-once data
            #pragma unroll
            for (int k = 0; k < 8; k++) s += dot4(a[k], w[k]);
            bg = bag[row];
        }
        // quad reduction: all 4 lanes of the quad end up with the row sum
        s += __shfl_xor_sync(0xFFFFFFFFu, s, 1);
        s += __shfl_xor_sync(0xFFFFFFFFu, s, 2);
        s += bias;

        // this lane's row key
        unsigned long long key = valid
            ? (((unsigned long long)ordered_float(s) << 32) | (unsigned)(~row))
            : 0ULL;

        if (valid && q == 0) loc_out[row] = s;

        // warp-aggregate: compare against the 8 quad representatives
        bool isFirst = true;                 // first quad with my bag id?
        unsigned long long aggKey = key;     // max key among same-bag quads
        #pragma unroll
        for (int j = 0; j < 8; j++) {
            int                bg_j  = __shfl_sync(0xFFFFFFFFu, bg,  j * 4);
            unsigned long long key_j = __shfl_sync(0xFFFFFFFFu, key, j * 4);
            if (bg_j == bg) {
                if (j < quad) isFirst = false;
                if (key_j > aggKey) aggKey = key_j;
            }
        }

        if (valid && q == 0 && isFirst)
            atomicMax(&g_keys[bg], aggKey);
    }
}

// 256 threads handle 2 bags (128 threads each): decode argmax, gather, reset.
__global__ void gather_kernel(const float* __restrict__ z,
                              const float* __restrict__ inst,
                              const float* __restrict__ mu,
                              const float* __restrict__ sd,
                              float* __restrict__ out) {
    const int half  = threadIdx.x >> 7;           // 0 or 1
    const int tid   = threadIdx.x & 127;          // 0..127 within half
    const int bagId = blockIdx.x * 2 + half;
    if (bagId >= BB) return;

    const unsigned long long key = g_keys[bagId];
    const bool empty = (key == 0ULL);
    int idx = (int)(~(unsigned)(key & 0xFFFFFFFFull));
    if (empty) idx = 0;

    // Output layout: M | max_instances | max_z_ins | loc_ins | max_mu | max_std
    float* M_out    = out;
    float* inst_out = out + BB;
    float* z_out    = inst_out + (size_t)BB * FF;
    float* loc_buf  = z_out    + (size_t)BB * DD;   // loc_ins (written by matvec)
    float* mu_out   = loc_buf  + NN;
    float* sd_out   = mu_out   + (size_t)BB * DD;

    const float4 zero4 = make_float4(0.f, 0.f, 0.f, 0.f);

    // max_instances: 128 float4, one per thread in this half
    {
        const float4* src = reinterpret_cast<const float4*>(inst + (size_t)idx * FF);
        float4* dst = reinterpret_cast<float4*>(inst_out + (size_t)bagId * FF);
        dst[tid] = empty ? zero4 : src[tid];
    }

    // z / mu / sd: 32 float4 each, disjoint 32-thread groups
    if (tid < 32) {
        const float4* src = reinterpret_cast<const float4*>(z + (size_t)idx * DD);
        float4* dst = reinterpret_cast<float4*>(z_out + (size_t)bagId * DD);
        dst[tid] = empty ? zero4 : src[tid];
    } else if (tid < 64) {
        const int t = tid - 32;
        const float4* src = reinterpret_cast<const float4*>(mu + (size_t)idx * DD);
        float4* dst = reinterpret_cast<float4*>(mu_out + (size_t)bagId * DD);
        dst[t] = empty ? zero4 : src[t];
    } else if (tid < 96) {
        const int t = tid - 64;
        const float4* src = reinterpret_cast<const float4*>(sd + (size_t)idx * DD);
        float4* dst = reinterpret_cast<float4*>(sd_out + (size_t)bagId * DD);
        dst[t] = empty ? zero4 : src[t];
    } else if (tid == 96) {
        M_out[bagId] = empty ? 0.0f : loc_buf[idx];
    } else if (tid == 97) {
        g_keys[bagId] = 0ULL;   // restore zero state for next graph replay
    }
}

extern "C" void kernel_launch(void* const* d_in, const int* in_sizes, int n_in,
                              void* d_out, int out_size) {
    const float* z    = (const float*)d_in[0]; // z_ins (N,D)
    const int*   bag  = (const int*)  d_in[1]; // bag_idx (N,)
    const float* inst = (const float*)d_in[2]; // bag_instances (N,F)
    const float* mu   = (const float*)d_in[3]; // instance_mu (N,D)
    const float* sd   = (const float*)d_in[4]; // instance_std (N,D)
    const float* W    = (const float*)d_in[5]; // (D,1)
    const float* b    = (const float*)d_in[6]; // (1,)
    float* out = (float*)d_out;

    const int n = in_sizes[1];

    float* loc_out = out + BB + (size_t)BB * FF + (size_t)BB * DD;

    matvec_argmax_kernel<<<2048, 256>>>(z, bag, W, b, loc_out, n);
    gather_kernel<<<(BB + 1) / 2, 256>>>(z, inst, mu, sd, out);
}

// round 4
// speedup vs baseline: 1.4073x; 1.0482x over previous
#include <cuda_runtime.h>
#include <cuda_bf16.h>
#include <stdint.h>

#define NN 250000
#define DD 128
#define FF 512
#define BB 5000

// Per-bag argmax keys: (ordered_float(loc) << 32) | ~row_index
// atomicMax picks max loc; ties -> max(~row) = min row.
// 0 is a safe "empty" sentinel. Zeroed at module load; gather_kernel re-zeros
// after consuming, so every graph replay starts from the all-zero state.
__device__ unsigned long long g_keys[BB];

__device__ __forceinline__ unsigned ordered_float(float f) {
    unsigned u = __float_as_uint(f);
    return u ^ (((int)u >> 31) | 0x80000000u);
}

__device__ __forceinline__ float dot4(float4 a, float4 b) {
    return fmaf(a.x, b.x, fmaf(a.y, b.y, fmaf(a.z, b.z, a.w * b.w)));
}

// Quad-per-row matvec. Each warp owns 16 CONTIGUOUS rows (2 iterations x 8
// rows), 15625 warps cover N=250000 exactly -> perfectly balanced work.
// bag_idx is sorted, so the 8 rows of an iteration span ~1 bag: aggregate
// argmax in-warp, one atomic per distinct bag.
__global__ void matvec_argmax_kernel(const float* __restrict__ z,
                                     const int*   __restrict__ bag,
                                     const float* __restrict__ W,
                                     const float* __restrict__ bptr,
                                     float* __restrict__ loc_out,
                                     int n) {
    const int lane = threadIdx.x & 31;
    const int q    = lane & 3;        // position within quad (0..3)
    const int quad = lane >> 2;       // quad id within warp (0..7)
    const int warp = (blockIdx.x * blockDim.x + threadIdx.x) >> 5;

    const int chunkBase = warp * 16;
    if (chunkBase >= n) return;

    // W registers: this lane needs W4[q + 4k], k=0..7
    const float4* W4 = reinterpret_cast<const float4*>(W);
    float4 w[8];
    #pragma unroll
    for (int k = 0; k < 8; k++) w[k] = W4[q + 4 * k];

    const float  bias = bptr[0];
    const float4* z4p = reinterpret_cast<const float4*>(z); // 32 float4 per row

    #pragma unroll
    for (int it = 0; it < 2; it++) {
        const int row = chunkBase + it * 8 + quad;
        const bool valid = (row < n);

        float s = 0.0f;
        int   bg = -1;
        if (valid) {
            const float4* zr = z4p + (size_t)row * 32;
            float4 a[8];
            #pragma unroll
            for (int k = 0; k < 8; k++)
                a[k] = __ldcs(zr + q + 4 * k);      // streaming read-once
            #pragma unroll
            for (int k = 0; k < 8; k++) s += dot4(a[k], w[k]);
            bg = bag[row];
        }
        // quad reduction: all 4 lanes of the quad get the row sum
        s += __shfl_xor_sync(0xFFFFFFFFu, s, 1);
        s += __shfl_xor_sync(0xFFFFFFFFu, s, 2);
        s += bias;

        unsigned long long key = valid
            ? (((unsigned long long)ordered_float(s) << 32) | (unsigned)(~row))
            : 0ULL;

        if (valid && q == 0) loc_out[row] = s;

        // warp-aggregate across the 8 quad representatives
        bool isFirst = true;
        unsigned long long aggKey = key;
        #pragma unroll
        for (int j = 0; j < 8; j++) {
            int                bg_j  = __shfl_sync(0xFFFFFFFFu, bg,  j * 4);
            unsigned long long key_j = __shfl_sync(0xFFFFFFFFu, key, j * 4);
            if (bg_j == bg) {
                if (j < quad) isFirst = false;
                if (key_j > aggKey) aggKey = key_j;
            }
        }

        if (valid && q == 0 && isFirst)
            atomicMax(&g_keys[bg], aggKey);
    }
}

// Warp-per-bag gather: 8 bags per 256-thread block. Each lane issues 7
// independent float4 loads (4 inst + z + mu + sd) -> MLP ~7 after the key.
__global__ void gather_kernel(const float* __restrict__ z,
                              const float* __restrict__ inst,
                              const float* __restrict__ mu,
                              const float* __restrict__ sd,
                              float* __restrict__ out) {
    const int warpId = threadIdx.x >> 5;          // 0..7
    const int lane   = threadIdx.x & 31;
    const int bagId  = blockIdx.x * 8 + warpId;
    if (bagId >= BB) return;

    // lane 0 reads the key and resets it (safe: only lane 0 touches it)
    unsigned long long key = 0ULL;
    if (lane == 0) {
        key = g_keys[bagId];
        g_keys[bagId] = 0ULL;   // restore zero state for next graph replay
    }
    key = __shfl_sync(0xFFFFFFFFu, key, 0);

    const bool empty = (key == 0ULL);
    int idx = (int)(~(unsigned)(key & 0xFFFFFFFFull));
    if (empty) idx = 0;

    // Output layout: M | max_instances | max_z_ins | loc_ins | max_mu | max_std
    float* M_out    = out;
    float* inst_out = out + BB;
    float* z_out    = inst_out + (size_t)BB * FF;
    float* loc_buf  = z_out    + (size_t)BB * DD;   // loc_ins (written by matvec)
    float* mu_out   = loc_buf  + NN;
    float* sd_out   = mu_out   + (size_t)BB * DD;

    const float4 zero4 = make_float4(0.f, 0.f, 0.f, 0.f);

    const float4* srcI = reinterpret_cast<const float4*>(inst + (size_t)idx * FF);
    const float4* srcZ = reinterpret_cast<const float4*>(z    + (size_t)idx * DD);
    const float4* srcM = reinterpret_cast<const float4*>(mu   + (size_t)idx * DD);
    const float4* srcS = reinterpret_cast<const float4*>(sd   + (size_t)idx * DD);

    // Issue all 7 loads first (independent -> MLP=7), then store.
    float4 vI0 = srcI[lane];
    float4 vI1 = srcI[lane + 32];
    float4 vI2 = srcI[lane + 64];
    float4 vI3 = srcI[lane + 96];
    float4 vZ  = srcZ[lane];
    float4 vM  = srcM[lane];
    float4 vS  = srcS[lane];
    float  m   = (lane == 0) ? loc_buf[idx] : 0.0f;

    if (empty) {
        vI0 = vI1 = vI2 = vI3 = vZ = vM = vS = zero4;
        m = 0.0f;
    }

    float4* dstI = reinterpret_cast<float4*>(inst_out + (size_t)bagId * FF);
    float4* dstZ = reinterpret_cast<float4*>(z_out    + (size_t)bagId * DD);
    float4* dstM = reinterpret_cast<float4*>(mu_out   + (size_t)bagId * DD);
    float4* dstS = reinterpret_cast<float4*>(sd_out   + (size_t)bagId * DD);

    dstI[lane]      = vI0;
    dstI[lane + 32] = vI1;
    dstI[lane + 64] = vI2;
    dstI[lane + 96] = vI3;
    dstZ[lane]      = vZ;
    dstM[lane]      = vM;
    dstS[lane]      = vS;
    if (lane == 0) M_out[bagId] = m;
}

extern "C" void kernel_launch(void* const* d_in, const int* in_sizes, int n_in,
                              void* d_out, int out_size) {
    const float* z    = (const float*)d_in[0]; // z_ins (N,D)
    const int*   bag  = (const int*)  d_in[1]; // bag_idx (N,)
    const float* inst = (const float*)d_in[2]; // bag_instances (N,F)
    const float* mu   = (const float*)d_in[3]; // instance_mu (N,D)
    const float* sd   = (const float*)d_in[4]; // instance_std (N,D)
    const float* W    = (const float*)d_in[5]; // (D,1)
    const float* b    = (const float*)d_in[6]; // (1,)
    float* out = (float*)d_out;

    const int n = in_sizes[1];

    float* loc_out = out + BB + (size_t)BB * FF + (size_t)BB * DD;

    // exact chunking: 1 warp per 16 rows
    const int warpsNeeded = (n + 15) / 16;               // 15625 for N=250000
    const int mvBlocks    = (warpsNeeded + 7) / 8;       // 8 warps per block

    matvec_argmax_kernel<<<mvBlocks, 256>>>(z, bag, W, b, loc_out, n);
    gather_kernel<<<(BB + 7) / 8, 256>>>(z, inst, mu, sd, out);
}